// round 4
// baseline (speedup 1.0000x reference)
#include <cuda_runtime.h>
#include <cuda_bf16.h>

// out[i] = input[segm_img[i]] : gather with a 1024-entry fp32 LUT over a
// 4096x4096 index image. Pure HBM streaming (~128-192 MB).
//
// Robustness: the index dtype may be int64 (as the reference declares) or
// int32 (JAX with x64 disabled silently downgrades randint to int32). A tiny
// probe kernel detects which: for little-endian int64 values in [0,1024),
// every odd 32-bit word is zero; for random int32 indices the odd words are
// random in [0,1024) and the OR over 1024 of them is nonzero with
// overwhelming probability. Inputs are identified by element count, not
// position, so d_in ordering cannot break us.

#define N_SEGM  1024
#define THREADS 512

__device__ int g_idx_is_64;   // 1 = int64 indices, 0 = int32 indices

__global__ void probe_dtype_kernel(const uint4* __restrict__ segm_v)
{
    // Inspect the first 512 uint4 (= 8 KB = first 1024 int64 elements or
    // first 2048 int32 elements; buffer holds 16.7M elements either way).
    __shared__ unsigned int acc;
    if (threadIdx.x == 0) acc = 0u;
    __syncthreads();

    unsigned int v = 0u;
    for (int i = threadIdx.x; i < 512; i += blockDim.x) {
        uint4 w = segm_v[i];
        v |= w.y | w.w;               // odd 32-bit words
    }
    atomicOr(&acc, v);
    __syncthreads();

    if (threadIdx.x == 0)
        g_idx_is_64 = (acc == 0u) ? 1 : 0;
}

__global__ __launch_bounds__(THREADS)
void superpixel2pixel_kernel(const float* __restrict__ lut_g,
                             const void*  __restrict__ segm,
                             float*       __restrict__ out,
                             int n4)   // number of 4-pixel groups
{
    __shared__ float lut[N_SEGM];
    for (int i = threadIdx.x; i < N_SEGM; i += THREADS)
        lut[i] = lut_g[i];

    const int is64 = g_idx_is_64;   // uniform load
    __syncthreads();

    int i = blockIdx.x * blockDim.x + threadIdx.x;
    if (i >= n4) return;

    float4 o;
    if (is64) {
        longlong4 v = reinterpret_cast<const longlong4*>(segm)[i];  // 32 B
        o.x = lut[(int)v.x & (N_SEGM - 1)];
        o.y = lut[(int)v.y & (N_SEGM - 1)];
        o.z = lut[(int)v.z & (N_SEGM - 1)];
        o.w = lut[(int)v.w & (N_SEGM - 1)];
    } else {
        int4 v = reinterpret_cast<const int4*>(segm)[i];            // 16 B
        o.x = lut[v.x & (N_SEGM - 1)];
        o.y = lut[v.y & (N_SEGM - 1)];
        o.z = lut[v.z & (N_SEGM - 1)];
        o.w = lut[v.w & (N_SEGM - 1)];
    }
    reinterpret_cast<float4*>(out)[i] = o;   // STG.E.128
}

// Scalar tail (only if out_size % 4 != 0; not the case for 4096*4096).
__global__ void superpixel2pixel_tail(const float* __restrict__ lut_g,
                                      const void*  __restrict__ segm,
                                      float*       __restrict__ out,
                                      int start, int n)
{
    int i = start + blockIdx.x * blockDim.x + threadIdx.x;
    if (i >= n) return;
    int idx;
    if (g_idx_is_64)
        idx = (int)reinterpret_cast<const long long*>(segm)[i];
    else
        idx = reinterpret_cast<const int*>(segm)[i];
    out[i] = lut_g[idx & (N_SEGM - 1)];
}

extern "C" void kernel_launch(void* const* d_in, const int* in_sizes, int n_in,
                              void* d_out, int out_size)
{
    // Identify inputs by element count (LUT = 1024, index image = 16.7M).
    int lut_idx = 0, seg_idx = 1;
    if (n_in >= 2 && in_sizes[0] > in_sizes[1]) { lut_idx = 1; seg_idx = 0; }

    const float* lut  = (const float*)d_in[lut_idx];
    const void*  segm = d_in[seg_idx];
    float*       out  = (float*)d_out;

    probe_dtype_kernel<<<1, 256>>>((const uint4*)segm);

    int n  = out_size;
    int n4 = n >> 2;
    if (n4 > 0) {
        int blocks = (n4 + THREADS - 1) / THREADS;
        superpixel2pixel_kernel<<<blocks, THREADS>>>(lut, segm, out, n4);
    }
    int rem_start = n4 << 2;
    if (n - rem_start > 0) {
        superpixel2pixel_tail<<<1, 256>>>(lut, segm, out, rem_start, n);
    }
}

// round 7
// speedup vs baseline: 1.1945x; 1.1945x over previous
#include <cuda_runtime.h>
#include <cuda_bf16.h>

// out[i] = input[segm_img[i]] : 1024-entry fp32 LUT gather over a 4096x4096
// index image. Pure HBM streaming (~128 MB with int32 indices).
//
// R4 evidence: indices are int32 (DRAM traffic ~91MB @ 42% BW), kernel was
// latency-bound (one LDG.128 per thread, 14 waves, nothing saturated).
// This round: (a) UNROLL=4 independent 16B loads per thread (front-batched
// -> MLP=4/thread, ~3.5 waves), (b) dtype probe folded into the main kernel
// per-CTA (kills the separate probe launch + its graph dependency),
// (c) unguarded fast path for full tiles so ptxas front-batches the LDGs.
//
// Dtype probe: for little-endian int64 values in [0,1024) every odd 32-bit
// word is zero; for random int32 indices the OR of 128 odd words is nonzero
// with probability 1 - 1024^-128. Each CTA probes the first 1KB (L2-hot).

#define N_SEGM  1024
#define THREADS 256
#define UNROLL  4
#define TILE    (THREADS * UNROLL)   // 4-pixel groups per block

__global__ __launch_bounds__(THREADS)
void superpixel2pixel_kernel(const float* __restrict__ lut_g,
                             const void*  __restrict__ segm,
                             float*       __restrict__ out,
                             int n4)   // number of 4-pixel groups
{
    __shared__ float lut[N_SEGM];
    __shared__ unsigned int probe_acc;

    if (threadIdx.x == 0) probe_acc = 0u;
    __syncthreads();

    // Per-CTA dtype probe: first 64 uint4 = 1 KB of the index buffer.
    if (threadIdx.x < 64) {
        uint4 w = reinterpret_cast<const uint4*>(segm)[threadIdx.x];
        unsigned int v = w.y | w.w;            // odd 32-bit words
        if (v) atomicOr(&probe_acc, v);
    }
    // LUT into shared (overlaps with probe).
    for (int i = threadIdx.x; i < N_SEGM; i += THREADS)
        lut[i] = lut_g[i];
    __syncthreads();

    const bool is64 = (probe_acc == 0u);       // uniform
    const int  i0   = blockIdx.x * TILE + threadIdx.x;
    const bool full = (blockIdx.x * TILE + TILE) <= n4;   // whole tile in range

    if (!is64) {
        // ---- int32 indices: 4 independent LDG.128 -> gather -> 4 STG.128
        int4 v[UNROLL];
        if (full) {
            #pragma unroll
            for (int k = 0; k < UNROLL; k++)
                v[k] = reinterpret_cast<const int4*>(segm)[i0 + k * THREADS];
            #pragma unroll
            for (int k = 0; k < UNROLL; k++) {
                float4 o;
                o.x = lut[v[k].x & (N_SEGM - 1)];
                o.y = lut[v[k].y & (N_SEGM - 1)];
                o.z = lut[v[k].z & (N_SEGM - 1)];
                o.w = lut[v[k].w & (N_SEGM - 1)];
                reinterpret_cast<float4*>(out)[i0 + k * THREADS] = o;
            }
        } else {
            #pragma unroll
            for (int k = 0; k < UNROLL; k++) {
                int i = i0 + k * THREADS;
                if (i < n4) {
                    int4 w = reinterpret_cast<const int4*>(segm)[i];
                    float4 o;
                    o.x = lut[w.x & (N_SEGM - 1)];
                    o.y = lut[w.y & (N_SEGM - 1)];
                    o.z = lut[w.z & (N_SEGM - 1)];
                    o.w = lut[w.w & (N_SEGM - 1)];
                    reinterpret_cast<float4*>(out)[i] = o;
                }
            }
        }
    } else {
        // ---- int64 indices: same structure, 32B per group
        longlong4 v[UNROLL];
        if (full) {
            #pragma unroll
            for (int k = 0; k < UNROLL; k++)
                v[k] = reinterpret_cast<const longlong4*>(segm)[i0 + k * THREADS];
            #pragma unroll
            for (int k = 0; k < UNROLL; k++) {
                float4 o;
                o.x = lut[(int)v[k].x & (N_SEGM - 1)];
                o.y = lut[(int)v[k].y & (N_SEGM - 1)];
                o.z = lut[(int)v[k].z & (N_SEGM - 1)];
                o.w = lut[(int)v[k].w & (N_SEGM - 1)];
                reinterpret_cast<float4*>(out)[i0 + k * THREADS] = o;
            }
        } else {
            #pragma unroll
            for (int k = 0; k < UNROLL; k++) {
                int i = i0 + k * THREADS;
                if (i < n4) {
                    longlong4 w = reinterpret_cast<const longlong4*>(segm)[i];
                    float4 o;
                    o.x = lut[(int)w.x & (N_SEGM - 1)];
                    o.y = lut[(int)w.y & (N_SEGM - 1)];
                    o.z = lut[(int)w.z & (N_SEGM - 1)];
                    o.w = lut[(int)w.w & (N_SEGM - 1)];
                    reinterpret_cast<float4*>(out)[i] = o;
                }
            }
        }
    }
}

// Scalar tail (only if out_size % 4 != 0; never for 4096*4096). Probes dtype
// itself so it has no dependency on any other kernel.
__global__ void superpixel2pixel_tail(const float* __restrict__ lut_g,
                                      const void*  __restrict__ segm,
                                      float*       __restrict__ out,
                                      int start, int n)
{
    __shared__ unsigned int probe_acc;
    if (threadIdx.x == 0) probe_acc = 0u;
    __syncthreads();
    if (threadIdx.x < 64) {
        uint4 w = reinterpret_cast<const uint4*>(segm)[threadIdx.x];
        unsigned int v = w.y | w.w;
        if (v) atomicOr(&probe_acc, v);
    }
    __syncthreads();
    const bool is64 = (probe_acc == 0u);

    int i = start + blockIdx.x * blockDim.x + threadIdx.x;
    if (i >= n) return;
    int idx;
    if (is64) idx = (int)reinterpret_cast<const long long*>(segm)[i];
    else      idx = reinterpret_cast<const int*>(segm)[i];
    out[i] = lut_g[idx & (N_SEGM - 1)];
}

extern "C" void kernel_launch(void* const* d_in, const int* in_sizes, int n_in,
                              void* d_out, int out_size)
{
    // Identify inputs by element count (LUT = 1024, index image = 16.7M).
    int lut_idx = 0, seg_idx = 1;
    if (n_in >= 2 && in_sizes[0] > in_sizes[1]) { lut_idx = 1; seg_idx = 0; }

    const float* lut  = (const float*)d_in[lut_idx];
    const void*  segm = d_in[seg_idx];
    float*       out  = (float*)d_out;

    int n  = out_size;
    int n4 = n >> 2;
    if (n4 > 0) {
        int blocks = (n4 + TILE - 1) / TILE;
        superpixel2pixel_kernel<<<blocks, THREADS>>>(lut, segm, out, n4);
    }
    int rem_start = n4 << 2;
    if (n - rem_start > 0) {
        superpixel2pixel_tail<<<1, 256>>>(lut, segm, out, rem_start, n);
    }
}

// round 9
// speedup vs baseline: 1.3007x; 1.0889x over previous
#include <cuda_runtime.h>
#include <cuda_bf16.h>

// out[i] = input[segm_img[i]] : 1024-entry fp32 LUT gather over a 4096x4096
// index image. Pure HBM streaming (~64MB idx read + 64MB write).
//
// R7 evidence: one-shot kernel (one chain/thread) was latency-bound:
// DRAM 45%, issue 20%, nothing saturated. This round: persistent grid
// (1 wave = 148x8 CTAs) + grid-stride loop with prefetch-next-iteration,
// so warps always have index loads in flight (steady-state streaming).
// __ldcs/__stcs: both streams are zero-reuse -> evict-first in L2.
// R8 fix: __ldcs has no longlong4 overload -> int64 path reads 2x uint4.
//
// Dtype probe (per-CTA, 1KB, L2-hot): int64 values in [0,1024) have all-zero
// odd 32-bit words; random int32 indices OR to nonzero w.p. 1 - 1024^-128.

#define N_SEGM  1024
#define THREADS 256
#define GPI     2                 // 16B-index groups per thread per iteration
#define MAX_BLOCKS 1184           // 148 SMs * 8 CTAs -> one wave

__global__ __launch_bounds__(THREADS, 8)
void superpixel2pixel_kernel(const float* __restrict__ lut_g,
                             const void*  __restrict__ segm,
                             float*       __restrict__ out,
                             int n4)   // number of 4-pixel groups
{
    __shared__ float lut[N_SEGM];
    __shared__ unsigned int probe_acc;

    if (threadIdx.x == 0) probe_acc = 0u;
    __syncthreads();

    if (threadIdx.x < 64) {
        uint4 w = reinterpret_cast<const uint4*>(segm)[threadIdx.x];
        unsigned int v = w.y | w.w;            // odd 32-bit words
        if (v) atomicOr(&probe_acc, v);
    }
    for (int i = threadIdx.x; i < N_SEGM; i += THREADS)
        lut[i] = lut_g[i];
    __syncthreads();

    const bool is64   = (probe_acc == 0u);     // uniform
    const int  stride = gridDim.x * THREADS * GPI;

    if (!is64) {
        const int4* sp = (const int4*)segm;
        int base = blockIdx.x * THREADS * GPI + threadIdx.x;

        // prologue: prefetch iteration 0
        int4 v[GPI];
        #pragma unroll
        for (int k = 0; k < GPI; k++) {
            int i = base + k * THREADS;
            if (i < n4) v[k] = __ldcs(sp + i);
        }

        while (base < n4) {
            int next = base + stride;
            // prefetch next iteration while current gathers/stores
            int4 nv[GPI];
            #pragma unroll
            for (int k = 0; k < GPI; k++) {
                int i = next + k * THREADS;
                if (i < n4) nv[k] = __ldcs(sp + i);
            }
            #pragma unroll
            for (int k = 0; k < GPI; k++) {
                int i = base + k * THREADS;
                if (i < n4) {
                    float4 o;
                    o.x = lut[v[k].x & (N_SEGM - 1)];
                    o.y = lut[v[k].y & (N_SEGM - 1)];
                    o.z = lut[v[k].z & (N_SEGM - 1)];
                    o.w = lut[v[k].w & (N_SEGM - 1)];
                    __stcs(reinterpret_cast<float4*>(out) + i, o);
                }
            }
            #pragma unroll
            for (int k = 0; k < GPI; k++) v[k] = nv[k];
            base = next;
        }
    } else {
        // int64 path: each 4-pixel group = 32 B = two uint4 streaming loads.
        const uint4* sp = (const uint4*)segm;   // 2 uint4 per group
        int base = blockIdx.x * THREADS * GPI + threadIdx.x;

        uint4 va[GPI], vb[GPI];
        #pragma unroll
        for (int k = 0; k < GPI; k++) {
            int i = base + k * THREADS;
            if (i < n4) {
                va[k] = __ldcs(sp + 2 * i);
                vb[k] = __ldcs(sp + 2 * i + 1);
            }
        }

        while (base < n4) {
            int next = base + stride;
            uint4 na[GPI], nb[GPI];
            #pragma unroll
            for (int k = 0; k < GPI; k++) {
                int i = next + k * THREADS;
                if (i < n4) {
                    na[k] = __ldcs(sp + 2 * i);
                    nb[k] = __ldcs(sp + 2 * i + 1);
                }
            }
            #pragma unroll
            for (int k = 0; k < GPI; k++) {
                int i = base + k * THREADS;
                if (i < n4) {
                    // low words of the 4 little-endian int64 values
                    float4 o;
                    o.x = lut[(int)va[k].x & (N_SEGM - 1)];
                    o.y = lut[(int)va[k].z & (N_SEGM - 1)];
                    o.z = lut[(int)vb[k].x & (N_SEGM - 1)];
                    o.w = lut[(int)vb[k].z & (N_SEGM - 1)];
                    __stcs(reinterpret_cast<float4*>(out) + i, o);
                }
            }
            #pragma unroll
            for (int k = 0; k < GPI; k++) { va[k] = na[k]; vb[k] = nb[k]; }
            base = next;
        }
    }
}

// Scalar tail (only if out_size % 4 != 0; never for 4096*4096).
__global__ void superpixel2pixel_tail(const float* __restrict__ lut_g,
                                      const void*  __restrict__ segm,
                                      float*       __restrict__ out,
                                      int start, int n)
{
    __shared__ unsigned int probe_acc;
    if (threadIdx.x == 0) probe_acc = 0u;
    __syncthreads();
    if (threadIdx.x < 64) {
        uint4 w = reinterpret_cast<const uint4*>(segm)[threadIdx.x];
        unsigned int v = w.y | w.w;
        if (v) atomicOr(&probe_acc, v);
    }
    __syncthreads();
    const bool is64 = (probe_acc == 0u);

    int i = start + blockIdx.x * blockDim.x + threadIdx.x;
    if (i >= n) return;
    int idx;
    if (is64) idx = (int)reinterpret_cast<const long long*>(segm)[i];
    else      idx = reinterpret_cast<const int*>(segm)[i];
    out[i] = lut_g[idx & (N_SEGM - 1)];
}

extern "C" void kernel_launch(void* const* d_in, const int* in_sizes, int n_in,
                              void* d_out, int out_size)
{
    // Identify inputs by element count (LUT = 1024, index image = 16.7M).
    int lut_idx = 0, seg_idx = 1;
    if (n_in >= 2 && in_sizes[0] > in_sizes[1]) { lut_idx = 1; seg_idx = 0; }

    const float* lut  = (const float*)d_in[lut_idx];
    const void*  segm = d_in[seg_idx];
    float*       out  = (float*)d_out;

    int n  = out_size;
    int n4 = n >> 2;
    if (n4 > 0) {
        int blocks = (n4 + THREADS * GPI - 1) / (THREADS * GPI);
        if (blocks > MAX_BLOCKS) blocks = MAX_BLOCKS;
        superpixel2pixel_kernel<<<blocks, THREADS>>>(lut, segm, out, n4);
    }
    int rem_start = n4 << 2;
    if (n - rem_start > 0) {
        superpixel2pixel_tail<<<1, 256>>>(lut, segm, out, rem_start, n);
    }
}